// round 5
// baseline (speedup 1.0000x reference)
#include <cuda_runtime.h>
#include <cuda_bf16.h>
#include <math.h>

#define Bc 4
#define Tc 1024
#define Mc 256
#define Cc 512
#define Hc 8
#define HDc 64
#define C3c 1536
#define BHc 32

// ---------------- scratch ----------------
__device__ float g_qkv_x[Bc * Tc * C3c];
__device__ float g_qkv_y[Bc * Mc * C3c];
__device__ float g_catt1[BHc * Tc];
__device__ float g_catt2[BHc * Mc];
__device__ float g_catt[(long)BHc * Tc * Mc];
__device__ float g_x2y[(long)BHc * Tc * Mc];
__device__ float g_y2x[(long)BHc * Tc * Mc];
__device__ float g_big[(long)BHc * Tc * Tc];
__device__ float g_cval[Bc * Tc * Cc];
__device__ float g_sval[Bc * Tc * Cc];
__device__ float g_gs[Bc * Tc * Cc];
__device__ float g_gc[Bc * Tc * Cc];
__device__ float g_z[Bc * Tc * Cc];
// pre-rounded copies of harness tensors
__device__ float g_xr[Bc * Tc * Cc];
__device__ float g_yr[Bc * Mc * Cc];
__device__ float g_wqx[Cc * C3c];
__device__ float g_wqy[Cc * C3c];
__device__ float g_wgs[Cc * Cc];
__device__ float g_wgc[Cc * Cc];
__device__ float g_wp[Cc * Cc];

// ---------------- helpers ----------------
__device__ __forceinline__ float rnd(float f) {
    unsigned u;
    asm("cvt.rna.tf32.f32 %0, %1;" : "=r"(u) : "f"(f));
    return __uint_as_float(u);
}
__device__ __forceinline__ void mma8(float* d, const unsigned* a, const unsigned* b) {
    asm volatile(
        "mma.sync.aligned.m16n8k8.row.col.f32.tf32.tf32.f32 "
        "{%0,%1,%2,%3},{%4,%5,%6,%7},{%8,%9},{%0,%1,%2,%3};"
        : "+f"(d[0]), "+f"(d[1]), "+f"(d[2]), "+f"(d[3])
        : "r"(a[0]), "r"(a[1]), "r"(a[2]), "r"(a[3]), "r"(b[0]), "r"(b[1]));
}
__device__ __forceinline__ void cpa16(unsigned dst, const void* src) {
    asm volatile("cp.async.cg.shared.global [%0], [%1], 16;" :: "r"(dst), "l"(src));
}
__device__ __forceinline__ void cpcommit() { asm volatile("cp.async.commit_group;"); }
__device__ __forceinline__ void ldsm4(unsigned& r0, unsigned& r1, unsigned& r2, unsigned& r3,
                                      unsigned addr) {
    asm volatile("ldmatrix.sync.aligned.m8n8.x4.shared.b16 {%0,%1,%2,%3},[%4];"
                 : "=r"(r0), "=r"(r1), "=r"(r2), "=r"(r3) : "r"(addr));
}

#define NT_STAGE (128 * 36)
#define NT_SMEM (4 * NT_STAGE * 4)
#define NN_ASTG (128 * 36)
#define NN_BSTG (32 * 68)
#define NN_SMEM ((2 * NN_ASTG + 2 * NN_BSTG) * 4)

extern __shared__ unsigned smem_u[];

// -------- pre-round fp32 -> tf32(RNA) stored as fp32, float4-vectorized --------
__global__ void round4(const float4* __restrict__ in, float4* __restrict__ out, int n4) {
    int i = blockIdx.x * blockDim.x + threadIdx.x;
    if (i < n4) {
        float4 v = in[i];
        out[i] = make_float4(rnd(v.x), rnd(v.y), rnd(v.z), rnd(v.w));
    }
}

// ================= NT GEMM: C = alpha * A(I,K) @ B(J,K)^T (+rb +cb) =================
// Inputs must be pre-rounded to tf32 (truncation exact). hasS path re-rounds after scale.
__global__ void __launch_bounds__(256, 2)
mma_nt(const float* __restrict__ A, long Abs, long Ahs, int ldA,
       const float* __restrict__ Bp, long Bbs, long Bhs, int ldB,
       const float* __restrict__ scaleA,
       const float* __restrict__ rbias, const float* __restrict__ cbias,
       float* __restrict__ Cp, int I, int J, int K, float alpha, int causal) {
    const int bh = blockIdx.z, b = bh >> 3, h = bh & 7;
    const int j0 = blockIdx.x * 128, i0 = blockIdx.y * 128;
    if (causal && j0 > i0) return;
    unsigned* As = smem_u;
    unsigned* Bs = smem_u + 2 * NT_STAGE;
    const unsigned sA0 = (unsigned)__cvta_generic_to_shared(As);
    const unsigned sB0 = (unsigned)__cvta_generic_to_shared(Bs);
    const float* Ab = A + (long)b * Abs + (long)h * Ahs + (long)i0 * ldA;
    const float* Bb = Bp + (long)b * Bbs + (long)h * Bhs + (long)j0 * ldB;

    const int tid = threadIdx.x, wid = tid >> 5, lane = tid & 31;
    const int g = lane >> 2, t = lane & 3;
    const int wm = (wid & 1) * 64, wn = (wid >> 1) * 32;
    const int lrow = lane & 15, lblk = lane >> 4;
    const int ldrow = tid >> 3, ldc4 = (tid & 7) * 4;

    float sreg[16];
    const bool hasS = (scaleA != nullptr);
    if (hasS) {
        const float* sA = scaleA + h * HDc;
        #pragma unroll
        for (int j = 0; j < 8; j++) {
            sreg[2 * j] = sA[8 * j + t];
            sreg[2 * j + 1] = sA[8 * j + t + 4];
        }
    }

    const int niter = K / 32;
    float acc[4][4][4] = {};

    {
        #pragma unroll
        for (int w = 0; w < 4; w++) {
            int r = ldrow + w * 32;
            cpa16(sA0 + (r * 36 + ldc4) * 4, Ab + (long)r * ldA + ldc4);
            cpa16(sB0 + (r * 36 + ldc4) * 4, Bb + (long)r * ldB + ldc4);
        }
        cpcommit();
    }

    for (int it = 0; it < niter; it++) {
        if (it + 1 < niter) {
            const int k0 = (it + 1) * 32, buf = (it + 1) & 1;
            #pragma unroll
            for (int w = 0; w < 4; w++) {
                int r = ldrow + w * 32;
                cpa16(sA0 + (buf * NT_STAGE + r * 36 + ldc4) * 4,
                      Ab + (long)r * ldA + k0 + ldc4);
                cpa16(sB0 + (buf * NT_STAGE + r * 36 + ldc4) * 4,
                      Bb + (long)r * ldB + k0 + ldc4);
            }
            cpcommit();
            asm volatile("cp.async.wait_group 1;");
        } else {
            asm volatile("cp.async.wait_group 0;");
        }
        __syncthreads();

        const int buf = it & 1;
        const unsigned aBase = sA0 + buf * NT_STAGE * 4;
        const unsigned bBase = sB0 + buf * NT_STAGE * 4;
        #pragma unroll
        for (int kk = 0; kk < 4; kk++) {
            const int kb = kk * 8 + 4 * lblk;
            unsigned a[4][4], bb[4][2];
            #pragma unroll
            for (int mf = 0; mf < 4; mf++)
                ldsm4(a[mf][0], a[mf][1], a[mf][2], a[mf][3],
                      aBase + ((wm + mf * 16 + lrow) * 36 + kb) * 4);
            #pragma unroll
            for (int p = 0; p < 2; p++) {
                unsigned r0, r1, r2, r3;
                ldsm4(r0, r1, r2, r3, bBase + ((wn + p * 16 + lrow) * 36 + kb) * 4);
                bb[2 * p][0] = r0;
                bb[2 * p][1] = r2;
                bb[2 * p + 1][0] = r1;
                bb[2 * p + 1][1] = r3;
            }
            if (hasS) {
                const int j = it * 4 + kk;
                const float slo = sreg[2 * j], shi = sreg[2 * j + 1];
                #pragma unroll
                for (int mf = 0; mf < 4; mf++) {
                    a[mf][0] = __float_as_uint(rnd(__uint_as_float(a[mf][0]) * slo));
                    a[mf][1] = __float_as_uint(rnd(__uint_as_float(a[mf][1]) * slo));
                    a[mf][2] = __float_as_uint(rnd(__uint_as_float(a[mf][2]) * shi));
                    a[mf][3] = __float_as_uint(rnd(__uint_as_float(a[mf][3]) * shi));
                }
            }
            #pragma unroll
            for (int mf = 0; mf < 4; mf++)
                #pragma unroll
                for (int nf = 0; nf < 4; nf++) mma8(acc[mf][nf], a[mf], bb[nf]);
        }
        __syncthreads();
    }

    float* Cb = Cp + (long)bh * I * J;
    const float* rb = rbias ? rbias + (long)bh * I : nullptr;
    const float* cb = cbias ? cbias + (long)bh * J : nullptr;
    #pragma unroll
    for (int mf = 0; mf < 4; mf++)
        #pragma unroll
        for (int nf = 0; nf < 4; nf++) {
            int r0 = i0 + wm + mf * 16 + g;
            int c0 = j0 + wn + nf * 8 + 2 * t;
            #pragma unroll
            for (int ep = 0; ep < 2; ep++) {
                int rr = r0 + ep * 8;
                float v0 = acc[mf][nf][2 * ep] * alpha;
                float v1 = acc[mf][nf][2 * ep + 1] * alpha;
                if (rb) { v0 += rb[rr]; v1 += rb[rr]; }
                if (cb) { v0 += cb[c0]; v1 += cb[c0 + 1]; }
                *(float2*)&Cb[(long)rr * J + c0] = make_float2(v0, v1);
            }
        }
}

// ================= NN GEMM: C = A(I,K) @ B(K,64-tile) (+bias) (+=) =================
__global__ void __launch_bounds__(256, 2)
mma_nn(const float* __restrict__ A, long Abs, long Ahs, int ldA,
       const float* __restrict__ Bp, long Bbs, long Bhs, int ldB,
       const float* __restrict__ bias,
       float* __restrict__ Cp, long Cbs, long Chs, int ldC,
       int K, int accumulate, int trailK, int roundOut) {
    const int bh = blockIdx.z, b = bh >> 3, h = bh & 7;
    const int col0 = blockIdx.x * 64, i0 = blockIdx.y * 128;
    unsigned* As = smem_u;
    unsigned* Bs = smem_u + 2 * NN_ASTG;
    const unsigned sA0 = (unsigned)__cvta_generic_to_shared(As);
    const unsigned sB0 = (unsigned)__cvta_generic_to_shared(Bs);
    const float* Ab = A + (long)b * Abs + (long)h * Ahs + (long)i0 * ldA;
    const float* Bb = Bp + (long)b * Bbs + (long)h * Bhs + col0;

    const int tid = threadIdx.x, wid = tid >> 5, lane = tid & 31;
    const int g = lane >> 2, t = lane & 3;
    const int wm = (wid & 1) * 64, wn = (wid >> 1) * 16;
    const int lrow = lane & 15, lblk = lane >> 4;
    const int ldrow = tid >> 3, ldc4 = (tid & 7) * 4;

    const int Keff = trailK ? min(K, i0 + 128) : K;
    const int niter = Keff / 32;
    float acc[4][2][4] = {};

    {
        #pragma unroll
        for (int w = 0; w < 4; w++) {
            int r = ldrow + w * 32;
            cpa16(sA0 + (r * 36 + ldc4) * 4, Ab + (long)r * ldA + ldc4);
        }
        #pragma unroll
        for (int w = 0; w < 2; w++) {
            int li = tid + w * 256;
            int r = li >> 4, c4 = (li & 15) * 4;
            cpa16(sB0 + (r * 68 + c4) * 4, Bb + (long)r * ldB + c4);
        }
        cpcommit();
    }

    for (int it = 0; it < niter; it++) {
        if (it + 1 < niter) {
            const int k0 = (it + 1) * 32, buf = (it + 1) & 1;
            #pragma unroll
            for (int w = 0; w < 4; w++) {
                int r = ldrow + w * 32;
                cpa16(sA0 + (buf * NN_ASTG + r * 36 + ldc4) * 4,
                      Ab + (long)r * ldA + k0 + ldc4);
            }
            #pragma unroll
            for (int w = 0; w < 2; w++) {
                int li = tid + w * 256;
                int r = li >> 4, c4 = (li & 15) * 4;
                cpa16(sB0 + (buf * NN_BSTG + r * 68 + c4) * 4,
                      Bb + (long)(k0 + r) * ldB + c4);
            }
            cpcommit();
            asm volatile("cp.async.wait_group 1;");
        } else {
            asm volatile("cp.async.wait_group 0;");
        }
        __syncthreads();

        const int buf = it & 1;
        const unsigned aBase = sA0 + buf * NN_ASTG * 4;
        const unsigned* Bbuf = Bs + buf * NN_BSTG;
        #pragma unroll
        for (int kk = 0; kk < 4; kk++) {
            const int kb8 = kk * 8;
            unsigned a[4][4], bb[2][2];
            #pragma unroll
            for (int mf = 0; mf < 4; mf++)
                ldsm4(a[mf][0], a[mf][1], a[mf][2], a[mf][3],
                      aBase + ((wm + mf * 16 + lrow) * 36 + kb8 + 4 * lblk) * 4);
            #pragma unroll
            for (int nf = 0; nf < 2; nf++) {
                bb[nf][0] = Bbuf[(kb8 + t) * 68 + wn + nf * 8 + g];
                bb[nf][1] = Bbuf[(kb8 + t + 4) * 68 + wn + nf * 8 + g];
            }
            #pragma unroll
            for (int mf = 0; mf < 4; mf++)
                #pragma unroll
                for (int nf = 0; nf < 2; nf++) mma8(acc[mf][nf], a[mf], bb[nf]);
        }
        __syncthreads();
    }

    float* Cb = Cp + (long)b * Cbs + (long)h * Chs + (long)i0 * ldC + col0;
    #pragma unroll
    for (int mf = 0; mf < 4; mf++)
        #pragma unroll
        for (int nf = 0; nf < 2; nf++) {
            int r0 = wm + mf * 16 + g;
            int c0 = wn + nf * 8 + 2 * t;
            #pragma unroll
            for (int e = 0; e < 4; e++) {
                int rr = r0 + (e >> 1) * 8;
                int cc = c0 + (e & 1);
                float v = acc[mf][nf][e];
                if (bias) v += bias[col0 + cc];
                long off = (long)rr * ldC + cc;
                if (accumulate) v += Cb[off];
                if (roundOut) v = rnd(v);
                Cb[off] = v;
            }
        }
}

// -------- catt1/catt2 dot products --------
__global__ void dotw(const float* __restrict__ qkv, const float* __restrict__ w,
                     int rows, float* __restrict__ out) {
    int gw = (blockIdx.x * blockDim.x + threadIdx.x) >> 5;
    int lane = threadIdx.x & 31;
    if (gw >= BHc * rows) return;
    int bh = gw / rows, r = gw % rows;
    int b = bh >> 3, h = bh & 7;
    const float* p = qkv + (long)(b * rows + r) * C3c + h * HDc;
    float s = p[lane] * w[h * HDc + lane] + p[lane + 32] * w[h * HDc + lane + 32];
    #pragma unroll
    for (int o = 16; o; o >>= 1) s += __shfl_xor_sync(0xffffffffu, s, o);
    if (lane == 0) out[gw] = s;
}

// -------- row softmax over M=256 (tf32-rounded output) --------
__global__ void softmax_row256(const float* __restrict__ in, float* __restrict__ out) {
    long row = blockIdx.x;
    int tid = threadIdx.x;
    __shared__ float sh[8];
    float v = in[row * 256 + tid];
    float m = v;
    #pragma unroll
    for (int o = 16; o; o >>= 1) m = fmaxf(m, __shfl_xor_sync(0xffffffffu, m, o));
    if ((tid & 31) == 0) sh[tid >> 5] = m;
    __syncthreads();
    float bm = sh[0];
    #pragma unroll
    for (int i = 1; i < 8; i++) bm = fmaxf(bm, sh[i]);
    __syncthreads();
    float e = expf(v - bm);
    float s = e;
    #pragma unroll
    for (int o = 16; o; o >>= 1) s += __shfl_xor_sync(0xffffffffu, s, o);
    if ((tid & 31) == 0) sh[tid >> 5] = s;
    __syncthreads();
    float bs = 0.f;
    #pragma unroll
    for (int i = 0; i < 8; i++) bs += sh[i];
    out[row * 256 + tid] = rnd(e / bs);
}

// -------- column softmax over T=1024 (tf32-rounded output) --------
__global__ void softmax_col(const float* __restrict__ in, float* __restrict__ out) {
    int bh = blockIdx.y;
    int mx = threadIdx.x & 63;
    int ty = threadIdx.x >> 6;
    int m = blockIdx.x * 64 + mx;
    const float* base = in + (long)bh * Tc * Mc + m;
    __shared__ float red[256];
    __shared__ float cstat[64];
    float acc = -3.4e38f;
    for (int t = ty; t < Tc; t += 4) acc = fmaxf(acc, base[(long)t * Mc]);
    red[threadIdx.x] = acc;
    __syncthreads();
    if (ty == 0)
        cstat[mx] = fmaxf(fmaxf(red[mx], red[64 + mx]), fmaxf(red[128 + mx], red[192 + mx]));
    __syncthreads();
    float cm = cstat[mx];
    __syncthreads();
    float s = 0.f;
    for (int t = ty; t < Tc; t += 4) s += expf(base[(long)t * Mc] - cm);
    red[threadIdx.x] = s;
    __syncthreads();
    if (ty == 0) cstat[mx] = red[mx] + red[64 + mx] + red[128 + mx] + red[192 + mx];
    __syncthreads();
    float inv = 1.f / cstat[mx];
    float* ob = out + (long)bh * Tc * Mc + m;
    for (int t = ty; t < Tc; t += 4) ob[(long)t * Mc] = rnd(expf(base[(long)t * Mc] - cm) * inv);
}

// -------- causal row softmax, trimmed to diagonal block, tf32-rounded --------
__global__ void softmax_causal(float* __restrict__ buf) {
    long row = blockIdx.x;
    int t = (int)(row & 1023);
    const int len = ((t >> 7) + 1) << 7;
    float* p = buf + row * 1024;
    int tid = threadIdx.x;
    __shared__ float sh[8];
    float v[4];
    float m = -3.4e38f;
    const int nchunk = (len + 255) >> 8;
    #pragma unroll 4
    for (int j = 0; j < nchunk; j++) {
        int s = tid + j * 256;
        float val = (s < len && s <= t) ? p[s] : -3.4e38f;
        v[j] = val;
        m = fmaxf(m, val);
    }
    #pragma unroll
    for (int o = 16; o; o >>= 1) m = fmaxf(m, __shfl_xor_sync(0xffffffffu, m, o));
    if ((tid & 31) == 0) sh[tid >> 5] = m;
    __syncthreads();
    float bm = sh[0];
    #pragma unroll
    for (int i = 1; i < 8; i++) bm = fmaxf(bm, sh[i]);
    __syncthreads();
    float sum = 0.f;
    #pragma unroll 4
    for (int j = 0; j < nchunk; j++) {
        int s = tid + j * 256;
        float e = (s < len && s <= t) ? expf(v[j] - bm) : 0.f;
        v[j] = e;
        sum += e;
    }
    #pragma unroll
    for (int o = 16; o; o >>= 1) sum += __shfl_xor_sync(0xffffffffu, sum, o);
    if ((tid & 31) == 0) sh[tid >> 5] = sum;
    __syncthreads();
    float bs = 0.f;
    #pragma unroll
    for (int i = 0; i < 8; i++) bs += sh[i];
    float inv = 1.f / bs;
    #pragma unroll 4
    for (int j = 0; j < nchunk; j++) {
        int s = tid + j * 256;
        if (s < len) p[s] = rnd(v[j] * inv);
    }
}

// -------- elementwise --------
__global__ void add_x(float* __restrict__ a, const float* __restrict__ b, int n) {
    int i = blockIdx.x * blockDim.x + threadIdx.x;
    if (i < n) a[i] = rnd(a[i] + b[i]);
}
__global__ void gate_combine(const float* __restrict__ gs, const float* __restrict__ gc,
                             const float* __restrict__ cval, const float* __restrict__ sval,
                             float* __restrict__ z, int n) {
    int i = blockIdx.x * blockDim.x + threadIdx.x;
    if (i < n) {
        float sg = 1.f / (1.f + expf(-gs[i]));
        float cg = 1.f / (1.f + expf(-gc[i]));
        z[i] = rnd(sg * cval[i] + cg * sval[i]);
    }
}

extern "C" void kernel_launch(void* const* d_in, const int* in_sizes, int n_in,
                              void* d_out, int out_size) {
    const float* x      = (const float*)d_in[0];
    const float* y      = (const float*)d_in[1];
    const float* Wqkv_x = (const float*)d_in[3];
    const float* bqkv_x = (const float*)d_in[4];
    const float* Wqkv_y = (const float*)d_in[5];
    const float* bqkv_y = (const float*)d_in[6];
    const float* w4x    = (const float*)d_in[7];
    const float* w4y    = (const float*)d_in[8];
    const float* w4xy   = (const float*)d_in[9];
    const float* Wgs    = (const float*)d_in[10];
    const float* bgs    = (const float*)d_in[11];
    const float* Wgc    = (const float*)d_in[12];
    const float* bgc    = (const float*)d_in[13];
    const float* Wp     = (const float*)d_in[14];
    const float* bp     = (const float*)d_in[15];
    float* out = (float*)d_out;

    cudaFuncSetAttribute(mma_nt, cudaFuncAttributeMaxDynamicSharedMemorySize, NT_SMEM);
    cudaFuncSetAttribute(mma_nn, cudaFuncAttributeMaxDynamicSharedMemorySize, NN_SMEM);

    float *p_qkv_x, *p_qkv_y, *p_catt1, *p_catt2, *p_catt, *p_x2y, *p_y2x,
          *p_big, *p_cval, *p_sval, *p_gs, *p_gc, *p_z,
          *p_xr, *p_yr, *p_wqx, *p_wqy, *p_wgs, *p_wgc, *p_wp;
    cudaGetSymbolAddress((void**)&p_qkv_x, g_qkv_x);
    cudaGetSymbolAddress((void**)&p_qkv_y, g_qkv_y);
    cudaGetSymbolAddress((void**)&p_catt1, g_catt1);
    cudaGetSymbolAddress((void**)&p_catt2, g_catt2);
    cudaGetSymbolAddress((void**)&p_catt, g_catt);
    cudaGetSymbolAddress((void**)&p_x2y, g_x2y);
    cudaGetSymbolAddress((void**)&p_y2x, g_y2x);
    cudaGetSymbolAddress((void**)&p_big, g_big);
    cudaGetSymbolAddress((void**)&p_cval, g_cval);
    cudaGetSymbolAddress((void**)&p_sval, g_sval);
    cudaGetSymbolAddress((void**)&p_gs, g_gs);
    cudaGetSymbolAddress((void**)&p_gc, g_gc);
    cudaGetSymbolAddress((void**)&p_z, g_z);
    cudaGetSymbolAddress((void**)&p_xr, g_xr);
    cudaGetSymbolAddress((void**)&p_yr, g_yr);
    cudaGetSymbolAddress((void**)&p_wqx, g_wqx);
    cudaGetSymbolAddress((void**)&p_wqy, g_wqy);
    cudaGetSymbolAddress((void**)&p_wgs, g_wgs);
    cudaGetSymbolAddress((void**)&p_wgc, g_wgc);
    cudaGetSymbolAddress((void**)&p_wp, g_wp);

    const float scale = 0.125f;
    const float invSqrtM = 0.0625f;

    // 0. pre-round harness tensors to tf32
    round4<<<(Bc * Tc * Cc) / 1024, 256>>>((const float4*)x, (float4*)p_xr, Bc * Tc * Cc / 4);
    round4<<<(Bc * Mc * Cc) / 1024, 256>>>((const float4*)y, (float4*)p_yr, Bc * Mc * Cc / 4);
    round4<<<(Cc * C3c) / 1024, 256>>>((const float4*)Wqkv_x, (float4*)p_wqx, Cc * C3c / 4);
    round4<<<(Cc * C3c) / 1024, 256>>>((const float4*)Wqkv_y, (float4*)p_wqy, Cc * C3c / 4);
    round4<<<(Cc * Cc) / 1024, 256>>>((const float4*)Wgs, (float4*)p_wgs, Cc * Cc / 4);
    round4<<<(Cc * Cc) / 1024, 256>>>((const float4*)Wgc, (float4*)p_wgc, Cc * Cc / 4);
    round4<<<(Cc * Cc) / 1024, 256>>>((const float4*)Wp, (float4*)p_wp, Cc * Cc / 4);

    // 1-2. QKV projections (rounded outputs)
    mma_nn<<<dim3(C3c / 64, (Bc * Tc) / 128, 1), 256, NN_SMEM>>>(
        p_xr, 0, 0, Cc, p_wqx, 0, 0, C3c, bqkv_x,
        p_qkv_x, 0, 0, C3c, Cc, 0, 0, 1);
    mma_nn<<<dim3(C3c / 64, (Bc * Mc) / 128, 1), 256, NN_SMEM>>>(
        p_yr, 0, 0, Cc, p_wqy, 0, 0, C3c, bqkv_y,
        p_qkv_y, 0, 0, C3c, Cc, 0, 0, 1);

    // 3. bias terms
    dotw<<<(BHc * Tc) / 8, 256>>>(p_qkv_x, w4x, Tc, p_catt1);
    dotw<<<(BHc * Mc) / 8, 256>>>(p_qkv_y, w4y, Mc, p_catt2);

    // 4. catt
    mma_nt<<<dim3(Mc / 128, Tc / 128, BHc), 256, NT_SMEM>>>(
        p_qkv_x, (long)Tc * C3c, 64, C3c,
        p_qkv_y + Cc, (long)Mc * C3c, 64, C3c,
        w4xy, p_catt1, p_catt2,
        p_catt, Tc, Mc, HDc, scale, 0);

    // 5-6. softmaxes (rounded outputs)
    softmax_row256<<<BHc * Tc, 256>>>(p_catt, p_x2y);
    softmax_col<<<dim3(Mc / 64, BHc), 256>>>(p_catt, p_y2x);

    // 7. cval_x2y = x2y @ v_y
    mma_nn<<<dim3(1, Tc / 128, BHc), 256, NN_SMEM>>>(
        p_x2y, 8L * Tc * Mc, (long)Tc * Mc, Mc,
        p_qkv_y + 2 * Cc, (long)Mc * C3c, 64, C3c, nullptr,
        p_cval, (long)Tc * Cc, 64, Cc, Mc, 0, 0, 0);

    // 8-9. chain
    mma_nt<<<dim3(Tc / 128, Tc / 128, BHc), 256, NT_SMEM>>>(
        p_x2y, 8L * Tc * Mc, (long)Tc * Mc, Mc,
        p_y2x, 8L * Tc * Mc, (long)Tc * Mc, Mc,
        nullptr, nullptr, nullptr,
        p_big, Tc, Tc, Mc, invSqrtM, 1);
    softmax_causal<<<BHc * Tc, 256>>>(p_big);

    // 10. cval += chain @ v_x (triangular K)
    mma_nn<<<dim3(1, Tc / 128, BHc), 256, NN_SMEM>>>(
        p_big, 8L * Tc * Tc, (long)Tc * Tc, Tc,
        p_qkv_x + 2 * Cc, (long)Tc * C3c, 64, C3c, nullptr,
        p_cval, (long)Tc * Cc, 64, Cc, Tc, 1, 1, 0);

    // 11. cval = rnd(cval + x)
    add_x<<<(Bc * Tc * Cc) / 256, 256>>>(p_cval, x, Bc * Tc * Cc);

    // 12-14. self-attention
    mma_nt<<<dim3(Tc / 128, Tc / 128, BHc), 256, NT_SMEM>>>(
        p_qkv_x, (long)Tc * C3c, 64, C3c,
        p_qkv_x + Cc, (long)Tc * C3c, 64, C3c,
        nullptr, nullptr, nullptr,
        p_big, Tc, Tc, HDc, scale, 1);
    softmax_causal<<<BHc * Tc, 256>>>(p_big);
    mma_nn<<<dim3(1, Tc / 128, BHc), 256, NN_SMEM>>>(
        p_big, 8L * Tc * Tc, (long)Tc * Tc, Tc,
        p_qkv_x + 2 * Cc, (long)Tc * C3c, 64, C3c, nullptr,
        p_sval, (long)Tc * Cc, 64, Cc, Tc, 0, 1, 1);

    // 15-16. gates
    mma_nn<<<dim3(Cc / 64, (Bc * Tc) / 128, 1), 256, NN_SMEM>>>(
        p_sval, 0, 0, Cc, p_wgs, 0, 0, Cc, bgs,
        p_gs, 0, 0, Cc, Cc, 0, 0, 0);
    mma_nn<<<dim3(Cc / 64, (Bc * Tc) / 128, 1), 256, NN_SMEM>>>(
        p_cval, 0, 0, Cc, p_wgc, 0, 0, Cc, bgc,
        p_gc, 0, 0, Cc, Cc, 0, 0, 0);

    // 17. combine (rounded z)
    gate_combine<<<(Bc * Tc * Cc) / 256, 256>>>(p_gs, p_gc, p_cval, p_sval, p_z,
                                                Bc * Tc * Cc);

    // 18. out
    mma_nn<<<dim3(Cc / 64, (Bc * Tc) / 128, 1), 256, NN_SMEM>>>(
        p_z, 0, 0, Cc, p_wp, 0, 0, Cc, bp,
        out, 0, 0, Cc, Cc, 0, 0, 0);
}